// round 8
// baseline (speedup 1.0000x reference)
#include <cuda_runtime.h>
#include <cuda_bf16.h>
#include <cstdint>

#define NB 16384

__device__ __nv_bfloat16 g_Wp_hi[3 * 256 * 1024];
__device__ __nv_bfloat16 g_Wp_lo[3 * 256 * 1024];
__device__ __nv_bfloat16 g_W2p_hi[3 * 4 * 256 * 64];
__device__ __nv_bfloat16 g_W2p_lo[3 * 4 * 256 * 64];
__device__ __nv_bfloat16 g_x_hi[3ull * NB * 1024];
__device__ __nv_bfloat16 g_x_lo[3ull * NB * 1024];
__device__ __nv_bfloat16 g_h_hi[3ull * NB * 256];
__device__ __nv_bfloat16 g_h_lo[3ull * NB * 256];
__device__ float         g_gates[3ull * NB * 12];

__device__ __forceinline__ uint32_t smem_u32(const void* p) {
    uint32_t a;
    asm("{ .reg .u64 t; cvta.to.shared.u64 t, %1; cvt.u32.u64 %0, t; }" : "=r"(a) : "l"(p));
    return a;
}
__device__ __forceinline__ void cp16s(uint32_t dst, const void* src) {
    asm volatile("cp.async.cg.shared.global [%0], [%1], 16;\n" :: "r"(dst), "l"(src));
}
__device__ __forceinline__ void cp16(void* dst, const void* src) { cp16s(smem_u32(dst), src); }
__device__ __forceinline__ void cp_commit() { asm volatile("cp.async.commit_group;\n"); }
__device__ __forceinline__ void cp_wait0()  { asm volatile("cp.async.wait_group 0;\n"); }
__device__ __forceinline__ void cp_wait1()  { asm volatile("cp.async.wait_group 1;\n"); }

__device__ __forceinline__ void ldsm4(unsigned* r, uint32_t a) {
    asm volatile("ldmatrix.sync.aligned.m8n8.x4.shared.b16 {%0,%1,%2,%3}, [%4];"
        : "=r"(r[0]), "=r"(r[1]), "=r"(r[2]), "=r"(r[3]) : "r"(a));
}
__device__ __forceinline__ void mma_bf16(float* c, const unsigned* a, unsigned b0, unsigned b1) {
    asm volatile(
        "mma.sync.aligned.m16n8k16.row.col.f32.bf16.bf16.f32 "
        "{%0,%1,%2,%3}, {%4,%5,%6,%7}, {%8,%9}, {%0,%1,%2,%3};\n"
        : "+f"(c[0]), "+f"(c[1]), "+f"(c[2]), "+f"(c[3])
        : "r"(a[0]), "r"(a[1]), "r"(a[2]), "r"(a[3]), "r"(b0), "r"(b1));
}
__device__ __forceinline__ __nv_bfloat162 split_hi2(float a, float b) {
    __nv_bfloat162 h; h.x = __float2bfloat16(a); h.y = __float2bfloat16(b); return h;
}
__device__ __forceinline__ __nv_bfloat162 split_lo2(float a, float b, __nv_bfloat162 h) {
    __nv_bfloat162 l;
    l.x = __float2bfloat16(a - __bfloat162float(h.x));
    l.y = __float2bfloat16(b - __bfloat162float(h.y));
    return l;
}

// ---------- packs ----------
__global__ void pack_w1_kernel(const float* __restrict__ W1A, const float* __restrict__ W1S,
                               const float* __restrict__ W1B)
{
    int idx = blockIdx.x * blockDim.x + threadIdx.x;
    if (idx >= 3 * 256 * 1024) return;
    int k = idx & 1023, n = (idx >> 10) & 255, g = idx >> 18;
    const float* W1 = (g == 0) ? W1A : (g == 1) ? W1S : W1B;
    float w = W1[((size_t)(n >> 6) * 1024 + k) * 64 + (n & 63)];
    __nv_bfloat16 hi = __float2bfloat16(w);
    g_Wp_hi[idx] = hi;
    g_Wp_lo[idx] = __float2bfloat16(w - __bfloat162float(hi));
}
__global__ void pack_w2_kernel(const float* __restrict__ W2A, const float* __restrict__ W2S,
                               const float* __restrict__ W2B)
{
    int idx = blockIdx.x * blockDim.x + threadIdx.x;
    if (idx >= 3 * 4 * 256 * 64) return;
    int k = idx & 63, d = (idx >> 6) & 255, e = (idx >> 14) & 3, g = idx >> 16;
    const float* W2 = (g == 0) ? W2A : (g == 1) ? W2S : W2B;
    float w = W2[((size_t)e * 64 + k) * 256 + d];
    __nv_bfloat16 hi = __float2bfloat16(w);
    g_W2p_hi[idx] = hi;
    g_W2p_lo[idx] = __float2bfloat16(w - __bfloat162float(hi));
}

// ---------- gates + x split: softmax(x @ Wg + bg); also write x as bf16 hi/lo ----------
__global__ __launch_bounds__(256)
void gate_kernel(const float* __restrict__ xA, const float* __restrict__ xS,
                 const float* __restrict__ xB,
                 const float* __restrict__ WgA, const float* __restrict__ bgA,
                 const float* __restrict__ WgS, const float* __restrict__ bgS,
                 const float* __restrict__ WgB, const float* __restrict__ bgB)
{
    __shared__ float sWg[12][1024];
    const int g = blockIdx.z;
    const int row0 = blockIdx.x * 64;
    const float* x  = (g == 0) ? xA  : (g == 1) ? xS  : xB;
    const float* Wg = (g == 0) ? WgA : (g == 1) ? WgS : WgB;
    const float* bg = (g == 0) ? bgA : (g == 1) ? bgS : bgB;
    const int G = (g == 1) ? 12 : 8;
    const int tid = threadIdx.x, lane = tid & 31, wid = tid >> 5;
    __nv_bfloat16* Xhi = g_x_hi + (size_t)g * NB * 1024;
    __nv_bfloat16* Xlo = g_x_lo + (size_t)g * NB * 1024;

    for (int i = tid; i < 12 * 1024; i += 256) {
        int j = i >> 10, k = i & 1023;
        sWg[j][k] = (j < G) ? Wg[(size_t)k * G + j] : 0.f;
    }
    __syncthreads();

    for (int rp = 0; rp < 4; rp++) {
        int r0 = row0 + wid * 8 + rp * 2;
        float a0[12], a1[12];
        #pragma unroll
        for (int j = 0; j < 12; j++) { a0[j] = 0.f; a1[j] = 0.f; }
        const float* xr0 = x + (size_t)r0 * 1024;
        const float* xr1 = xr0 + 1024;
        for (int k4 = lane * 4; k4 < 1024; k4 += 128) {
            float4 v0 = *reinterpret_cast<const float4*>(xr0 + k4);
            float4 v1 = *reinterpret_cast<const float4*>(xr1 + k4);
            #pragma unroll
            for (int j = 0; j < 12; j++) {
                float4 wv = *reinterpret_cast<const float4*>(&sWg[j][k4]);
                a0[j] += v0.x * wv.x + v0.y * wv.y + v0.z * wv.z + v0.w * wv.w;
                a1[j] += v1.x * wv.x + v1.y * wv.y + v1.z * wv.z + v1.w * wv.w;
            }
            // split-store x as bf16 hi/lo
            {
                __nv_bfloat162 h01 = split_hi2(v0.x, v0.y), h23 = split_hi2(v0.z, v0.w);
                __nv_bfloat162 l01 = split_lo2(v0.x, v0.y, h01), l23 = split_lo2(v0.z, v0.w, h23);
                uint2 ph; ph.x = *reinterpret_cast<unsigned*>(&h01); ph.y = *reinterpret_cast<unsigned*>(&h23);
                uint2 pl; pl.x = *reinterpret_cast<unsigned*>(&l01); pl.y = *reinterpret_cast<unsigned*>(&l23);
                *reinterpret_cast<uint2*>(Xhi + (size_t)r0 * 1024 + k4) = ph;
                *reinterpret_cast<uint2*>(Xlo + (size_t)r0 * 1024 + k4) = pl;
            }
            {
                __nv_bfloat162 h01 = split_hi2(v1.x, v1.y), h23 = split_hi2(v1.z, v1.w);
                __nv_bfloat162 l01 = split_lo2(v1.x, v1.y, h01), l23 = split_lo2(v1.z, v1.w, h23);
                uint2 ph; ph.x = *reinterpret_cast<unsigned*>(&h01); ph.y = *reinterpret_cast<unsigned*>(&h23);
                uint2 pl; pl.x = *reinterpret_cast<unsigned*>(&l01); pl.y = *reinterpret_cast<unsigned*>(&l23);
                *reinterpret_cast<uint2*>(Xhi + (size_t)(r0 + 1) * 1024 + k4) = ph;
                *reinterpret_cast<uint2*>(Xlo + (size_t)(r0 + 1) * 1024 + k4) = pl;
            }
        }
        #pragma unroll
        for (int j = 0; j < 12; j++) {
            #pragma unroll
            for (int off = 16; off > 0; off >>= 1) {
                a0[j] += __shfl_xor_sync(0xffffffffu, a0[j], off);
                a1[j] += __shfl_xor_sync(0xffffffffu, a1[j], off);
            }
        }
        if (lane == 0) {
            for (int rr = 0; rr < 2; rr++) {
                float* ac = rr ? a1 : a0;
                float lg[12], m = -1e30f;
                for (int j = 0; j < G; j++) { lg[j] = ac[j] + bg[j]; m = fmaxf(m, lg[j]); }
                float s = 0.f;
                for (int j = 0; j < G; j++) { lg[j] = expf(lg[j] - m); s += lg[j]; }
                float inv = 1.f / s;
                float* dst = g_gates + ((size_t)g * NB + r0 + rr) * 12;
                for (int j = 0; j < G; j++) dst[j] = lg[j] * inv;
            }
        }
    }
}

// ---------- layer 1: pure-async 3-stage HMMA ----------
// stage (bf16 elems): Ah@0 (128x40), Al@5120, Bh@10240 (256x40), Bl@20480; stage size 30720
#define ST_ELEMS 30720
#define L1_SM (3 * ST_ELEMS * 2)   // 184320 B

__global__ __launch_bounds__(256, 1)
void layer1_kernel(const float* __restrict__ b1A, const float* __restrict__ b1S,
                   const float* __restrict__ b1B)
{
    extern __shared__ __nv_bfloat16 sm1[];
    const int tid = threadIdx.x;
    const int g = blockIdx.z;
    const int row0 = blockIdx.x * 128;
    const float* b1 = (g == 0) ? b1A : (g == 1) ? b1S : b1B;
    const __nv_bfloat16* Xhi = g_x_hi + ((size_t)g * NB + row0) * 1024;
    const __nv_bfloat16* Xlo = g_x_lo + ((size_t)g * NB + row0) * 1024;
    const __nv_bfloat16* WpHi = g_Wp_hi + (size_t)g * 256 * 1024;
    const __nv_bfloat16* WpLo = g_Wp_lo + (size_t)g * 256 * 1024;

    const int lane = tid & 31, wid = tid >> 5;
    const int gid = lane >> 2, quad = lane & 3;
    const int wm = wid & 3, wn = wid >> 2;
    const int a_row = (lane & 7) + ((lane >> 3) & 1) * 8;
    const int a_col = (lane >> 4) * 8;
    const int b_row = (lane & 7) + (lane >> 4) * 8;
    const int b_col = ((lane >> 3) & 1) * 8;

    float acc[2][16][4];
    #pragma unroll
    for (int mt = 0; mt < 2; mt++)
        #pragma unroll
        for (int nt = 0; nt < 16; nt++)
            #pragma unroll
            for (int q = 0; q < 4; q++) acc[mt][nt][q] = 0.f;

    auto loadC = [&](int c, int s) {
        int k0 = c * 32;
        __nv_bfloat16* st = sm1 + s * ST_ELEMS;
        #pragma unroll
        for (int i = 0; i < 12; i++) {
            int u = tid + i * 256;           // 0..3071
            if (u < 1024) {
                int sel = u >> 9;            // 0:hi 1:lo
                int j = u & 511;
                int r = j >> 2, cc = j & 3;
                const __nv_bfloat16* src = (sel ? Xlo : Xhi) + (size_t)r * 1024 + k0 + cc * 8;
                cp16(st + sel * 5120 + r * 40 + cc * 8, src);
            } else {
                int v = u - 1024;            // 0..2047
                int sel = v >> 10;
                int j = v & 1023;
                int n = j >> 2, cc = j & 3;
                const __nv_bfloat16* src = (sel ? WpLo : WpHi) + (size_t)n * 1024 + k0 + cc * 8;
                cp16(st + 10240 + sel * 10240 + n * 40 + cc * 8, src);
            }
        }
        cp_commit();
    };

    auto compute = [&](int s) {
        const __nv_bfloat16* Ah = sm1 + s * ST_ELEMS;
        const __nv_bfloat16* Al = Ah + 5120;
        const __nv_bfloat16* Bh = Ah + 10240;
        const __nv_bfloat16* Bl = Ah + 20480;
        #pragma unroll
        for (int ks = 0; ks < 2; ks++) {
            int kb = ks * 16;
            unsigned ah[2][4], al[2][4];
            #pragma unroll
            for (int mt = 0; mt < 2; mt++) {
                int r = wm * 32 + mt * 16 + a_row;
                ldsm4(ah[mt], smem_u32(Ah + r * 40 + kb + a_col));
                ldsm4(al[mt], smem_u32(Al + r * 40 + kb + a_col));
            }
            #pragma unroll
            for (int ntp = 0; ntp < 8; ntp++) {
                int n = wn * 128 + ntp * 16 + b_row;
                unsigned bh[4], bl[4];
                ldsm4(bh, smem_u32(Bh + n * 40 + kb + b_col));
                ldsm4(bl, smem_u32(Bl + n * 40 + kb + b_col));
                #pragma unroll
                for (int mt = 0; mt < 2; mt++) {
                    mma_bf16(acc[mt][2 * ntp],     ah[mt], bh[0], bh[1]);
                    mma_bf16(acc[mt][2 * ntp],     ah[mt], bl[0], bl[1]);
                    mma_bf16(acc[mt][2 * ntp],     al[mt], bh[0], bh[1]);
                    mma_bf16(acc[mt][2 * ntp + 1], ah[mt], bh[2], bh[3]);
                    mma_bf16(acc[mt][2 * ntp + 1], ah[mt], bl[2], bl[3]);
                    mma_bf16(acc[mt][2 * ntp + 1], al[mt], bh[2], bh[3]);
                }
            }
        }
    };

    loadC(0, 0);
    loadC(1, 1);

    #pragma unroll 1
    for (int c = 0; c < 32; c++) {
        if (c < 31) cp_wait1(); else cp_wait0();
        __syncthreads();
        if (c + 2 < 32) loadC(c + 2, (c + 2) % 3);
        compute(c % 3);
    }

    __nv_bfloat16* Hhi = g_h_hi + (size_t)g * NB * 256;
    __nv_bfloat16* Hlo = g_h_lo + (size_t)g * NB * 256;
    #pragma unroll
    for (int mt = 0; mt < 2; mt++) {
        #pragma unroll
        for (int nt = 0; nt < 16; nt++) {
            int col = wn * 128 + nt * 8 + quad * 2;
            float2 bv = *reinterpret_cast<const float2*>(b1 + col);
            #pragma unroll
            for (int p = 0; p < 2; p++) {
                int row = row0 + wm * 32 + mt * 16 + gid + p * 8;
                float v0 = fmaxf(acc[mt][nt][p * 2 + 0] + bv.x, 0.f);
                float v1 = fmaxf(acc[mt][nt][p * 2 + 1] + bv.y, 0.f);
                __nv_bfloat162 PH = split_hi2(v0, v1);
                __nv_bfloat162 PL = split_lo2(v0, v1, PH);
                size_t base = (size_t)row * 256 + col;
                *reinterpret_cast<__nv_bfloat162*>(Hhi + base) = PH;
                *reinterpret_cast<__nv_bfloat162*>(Hlo + base) = PL;
            }
        }
    }
}

// ---------- layer 2 + combine (as R7) ----------
#define L2_SH 0
#define L2_SW 36864
#define L2_SG 73728
#define L2_SM 82944
#define L2_STG 18432

__global__ __launch_bounds__(256, 1)
void layer2_kernel(const float* __restrict__ b2A, const float* __restrict__ b2S,
                   const float* __restrict__ b2B, float* __restrict__ out)
{
    extern __shared__ char sm2[];
    __nv_bfloat16* shb = reinterpret_cast<__nv_bfloat16*>(sm2 + L2_SH);
    __nv_bfloat16* swb = reinterpret_cast<__nv_bfloat16*>(sm2 + L2_SW);
    float* sg = reinterpret_cast<float*>(sm2 + L2_SG);

    const int tid = threadIdx.x;
    const int d0 = blockIdx.x * 64;
    const int row0 = blockIdx.y * 64;
    const int lane = tid & 31, wid = tid >> 5;
    const int gid = lane >> 2, quad = lane & 3;
    const int wm = wid & 1, wn = wid >> 1;

    const int a_row = (lane & 7) + ((lane >> 3) & 1) * 8;
    const int a_col = (lane >> 4) * 8;
    const int b_row = (lane & 7) + (lane >> 4) * 8;
    const int b_col = ((lane >> 3) & 1) * 8;

    for (int i = tid; i < 3 * 64 * 12; i += 256) {
        int gg = i / 768, r = (i / 12) & 63, j = i % 12;
        sg[(gg * 64 + r) * 12 + j] = g_gates[((size_t)gg * NB + row0 + r) * 12 + j];
    }

    auto prefetch = [&](int ge, int s) {
        int g = ge >> 2, e = ge & 3;
        const __nv_bfloat16* Hhi = g_h_hi + (size_t)g * NB * 256;
        const __nv_bfloat16* Hlo = g_h_lo + (size_t)g * NB * 256;
        const __nv_bfloat16* Whi = g_W2p_hi + ((size_t)(g * 4 + e) * 256 + d0) * 64;
        const __nv_bfloat16* Wlo = g_W2p_lo + ((size_t)(g * 4 + e) * 256 + d0) * 64;
        __nv_bfloat16* shs = shb + s * (L2_STG / 2);
        __nv_bfloat16* sws = swb + s * (L2_STG / 2);
        #pragma unroll
        for (int i = 0; i < 2; i++) {
            int idx = tid + i * 256;
            int r = idx >> 3, c = idx & 7;
            cp16(shs + r * 72 + c * 8,        Hhi + (size_t)(row0 + r) * 256 + e * 64 + c * 8);
            cp16(shs + 4608 + r * 72 + c * 8, Hlo + (size_t)(row0 + r) * 256 + e * 64 + c * 8);
            cp16(sws + r * 72 + c * 8,        Whi + (size_t)r * 64 + c * 8);
            cp16(sws + 4608 + r * 72 + c * 8, Wlo + (size_t)r * 64 + c * 8);
        }
        cp_commit();
    };

    float oA[2][2][4], oS[2][2][4], oB[2][2][4];
    #pragma unroll
    for (int mt = 0; mt < 2; mt++)
        #pragma unroll
        for (int nt = 0; nt < 2; nt++)
            #pragma unroll
            for (int q = 0; q < 4; q++) { oA[mt][nt][q] = 0.f; oS[mt][nt][q] = 0.f; oB[mt][nt][q] = 0.f; }

    prefetch(0, 0);
    __syncthreads();

    #pragma unroll 1
    for (int ge = 0; ge < 12; ge++) {
        int s = ge & 1;
        int g = ge >> 2, e = ge & 3;
        if (ge < 11) { prefetch(ge + 1, s ^ 1); cp_wait1(); }
        else cp_wait0();
        __syncthreads();

        const __nv_bfloat16* shs = shb + s * (L2_STG / 2);
        const __nv_bfloat16* sws = swb + s * (L2_STG / 2);

        float t[2][2][4];
        #pragma unroll
        for (int mt = 0; mt < 2; mt++)
            #pragma unroll
            for (int nt = 0; nt < 2; nt++)
                #pragma unroll
                for (int q = 0; q < 4; q++) t[mt][nt][q] = 0.f;

        #pragma unroll
        for (int ks = 0; ks < 4; ks++) {
            int kb = ks * 16;
            unsigned ah[2][4], al[2][4];
            #pragma unroll
            for (int mt = 0; mt < 2; mt++) {
                int r = wm * 32 + mt * 16 + a_row;
                ldsm4(ah[mt], smem_u32(shs + r * 72 + kb + a_col));
                ldsm4(al[mt], smem_u32(shs + 4608 + r * 72 + kb + a_col));
            }
            int n = wn * 16 + b_row;
            unsigned bh[4], bl[4];
            ldsm4(bh, smem_u32(sws + n * 72 + kb + b_col));
            ldsm4(bl, smem_u32(sws + 4608 + n * 72 + kb + b_col));
            #pragma unroll
            for (int mt = 0; mt < 2; mt++) {
                mma_bf16(t[mt][0], ah[mt], bh[0], bh[1]);
                mma_bf16(t[mt][0], ah[mt], bl[0], bl[1]);
                mma_bf16(t[mt][0], al[mt], bh[0], bh[1]);
                mma_bf16(t[mt][1], ah[mt], bh[2], bh[3]);
                mma_bf16(t[mt][1], ah[mt], bl[2], bl[3]);
                mma_bf16(t[mt][1], al[mt], bh[2], bh[3]);
            }
        }

        const float* b2 = (g == 0) ? b2A : (g == 1) ? b2S : b2B;
        #pragma unroll
        for (int mt = 0; mt < 2; mt++) {
            #pragma unroll
            for (int nt = 0; nt < 2; nt++) {
                int col = wn * 16 + nt * 8 + quad * 2;
                float2 bv = *reinterpret_cast<const float2*>(b2 + e * 256 + d0 + col);
                #pragma unroll
                for (int p = 0; p < 2; p++) {
                    int r = wm * 32 + mt * 16 + gid + p * 8;
                    float v0 = fmaxf(t[mt][nt][p * 2 + 0] + bv.x, 0.f);
                    float v1 = fmaxf(t[mt][nt][p * 2 + 1] + bv.y, 0.f);
                    if (g == 0) {
                        float ga = sg[(0 * 64 + r) * 12 + e], gs = sg[(1 * 64 + r) * 12 + e];
                        oA[mt][nt][p * 2 + 0] += ga * v0; oA[mt][nt][p * 2 + 1] += ga * v1;
                        oS[mt][nt][p * 2 + 0] += gs * v0; oS[mt][nt][p * 2 + 1] += gs * v1;
                    } else if (g == 1) {
                        float ga = sg[(0 * 64 + r) * 12 + 4 + e];
                        float gs = sg[(1 * 64 + r) * 12 + 4 + e];
                        float gb = sg[(2 * 64 + r) * 12 + 4 + e];
                        oA[mt][nt][p * 2 + 0] += ga * v0; oA[mt][nt][p * 2 + 1] += ga * v1;
                        oS[mt][nt][p * 2 + 0] += gs * v0; oS[mt][nt][p * 2 + 1] += gs * v1;
                        oB[mt][nt][p * 2 + 0] += gb * v0; oB[mt][nt][p * 2 + 1] += gb * v1;
                    } else {
                        float gs = sg[(1 * 64 + r) * 12 + 8 + e];
                        float gb = sg[(2 * 64 + r) * 12 + e];
                        oS[mt][nt][p * 2 + 0] += gs * v0; oS[mt][nt][p * 2 + 1] += gs * v1;
                        oB[mt][nt][p * 2 + 0] += gb * v0; oB[mt][nt][p * 2 + 1] += gb * v1;
                    }
                }
            }
        }
        __syncthreads();
    }

    #pragma unroll
    for (int mt = 0; mt < 2; mt++) {
        #pragma unroll
        for (int nt = 0; nt < 2; nt++) {
            int col = d0 + wn * 16 + nt * 8 + quad * 2;
            #pragma unroll
            for (int p = 0; p < 2; p++) {
                int row = row0 + wm * 32 + mt * 16 + gid + p * 8;
                size_t base = (size_t)row * 256 + col;
                float2 vA; vA.x = oA[mt][nt][p * 2]; vA.y = oA[mt][nt][p * 2 + 1];
                float2 vS; vS.x = oS[mt][nt][p * 2]; vS.y = oS[mt][nt][p * 2 + 1];
                float2 vB; vB.x = oB[mt][nt][p * 2]; vB.y = oB[mt][nt][p * 2 + 1];
                *reinterpret_cast<float2*>(out + base) = vA;
                *reinterpret_cast<float2*>(out + (size_t)NB * 256 + base) = vS;
                *reinterpret_cast<float2*>(out + 2ull * NB * 256 + base) = vB;
            }
        }
    }
}

extern "C" void kernel_launch(void* const* d_in, const int* in_sizes, int n_in,
                              void* d_out, int out_size)
{
    const float* xA  = (const float*)d_in[0];
    const float* xS  = (const float*)d_in[1];
    const float* xB  = (const float*)d_in[2];
    const float* W1A = (const float*)d_in[3];
    const float* b1A = (const float*)d_in[4];
    const float* W2A = (const float*)d_in[5];
    const float* b2A = (const float*)d_in[6];
    const float* W1S = (const float*)d_in[7];
    const float* b1S = (const float*)d_in[8];
    const float* W2S = (const float*)d_in[9];
    const float* b2S = (const float*)d_in[10];
    const float* W1B = (const float*)d_in[11];
    const float* b1B = (const float*)d_in[12];
    const float* W2B = (const float*)d_in[13];
    const float* b2B = (const float*)d_in[14];
    const float* WgA = (const float*)d_in[15];
    const float* bgA = (const float*)d_in[16];
    const float* WgB = (const float*)d_in[17];
    const float* bgB = (const float*)d_in[18];
    const float* WgS = (const float*)d_in[19];
    const float* bgS = (const float*)d_in[20];
    float* out = (float*)d_out;

    pack_w1_kernel<<<(3 * 256 * 1024 + 255) / 256, 256>>>(W1A, W1S, W1B);
    pack_w2_kernel<<<(3 * 4 * 256 * 64 + 255) / 256, 256>>>(W2A, W2S, W2B);
    gate_kernel<<<dim3(NB / 64, 1, 3), 256>>>(xA, xS, xB, WgA, bgA, WgS, bgS, WgB, bgB);

    cudaFuncSetAttribute(layer1_kernel, cudaFuncAttributeMaxDynamicSharedMemorySize, L1_SM);
    layer1_kernel<<<dim3(NB / 128, 1, 3), 256, L1_SM>>>(b1A, b1S, b1B);

    cudaFuncSetAttribute(layer2_kernel, cudaFuncAttributeMaxDynamicSharedMemorySize, L2_SM);
    layer2_kernel<<<dim3(256 / 64, NB / 64), 256, L2_SM>>>(b2A, b2S, b2B, out);
}

// round 9
// speedup vs baseline: 1.2422x; 1.2422x over previous
#include <cuda_runtime.h>
#include <cuda_bf16.h>
#include <cuda_fp16.h>
#include <cstdint>

#define NB 16384

__device__ __half         g_Wp[3 * 256 * 1024];          // W1 fp16 (single)
__device__ __nv_bfloat16  g_W2p_hi[3 * 4 * 256 * 64];
__device__ __nv_bfloat16  g_W2p_lo[3 * 4 * 256 * 64];
__device__ __nv_bfloat16  g_h_hi[3ull * NB * 256];
__device__ __nv_bfloat16  g_h_lo[3ull * NB * 256];
__device__ float          g_gates[3ull * NB * 12];

__device__ __forceinline__ uint32_t smem_u32(const void* p) {
    uint32_t a;
    asm("{ .reg .u64 t; cvta.to.shared.u64 t, %1; cvt.u32.u64 %0, t; }" : "=r"(a) : "l"(p));
    return a;
}
__device__ __forceinline__ void cp16s(uint32_t dst, const void* src) {
    asm volatile("cp.async.cg.shared.global [%0], [%1], 16;\n" :: "r"(dst), "l"(src));
}
__device__ __forceinline__ void cp16(void* dst, const void* src) { cp16s(smem_u32(dst), src); }
__device__ __forceinline__ void cp_commit() { asm volatile("cp.async.commit_group;\n"); }
__device__ __forceinline__ void cp_wait0()  { asm volatile("cp.async.wait_group 0;\n"); }
__device__ __forceinline__ void cp_wait1()  { asm volatile("cp.async.wait_group 1;\n"); }

__device__ __forceinline__ void ldsm4(unsigned* r, uint32_t a) {
    asm volatile("ldmatrix.sync.aligned.m8n8.x4.shared.b16 {%0,%1,%2,%3}, [%4];"
        : "=r"(r[0]), "=r"(r[1]), "=r"(r[2]), "=r"(r[3]) : "r"(a));
}
__device__ __forceinline__ void mma_bf16(float* c, const unsigned* a, unsigned b0, unsigned b1) {
    asm volatile(
        "mma.sync.aligned.m16n8k16.row.col.f32.bf16.bf16.f32 "
        "{%0,%1,%2,%3}, {%4,%5,%6,%7}, {%8,%9}, {%0,%1,%2,%3};\n"
        : "+f"(c[0]), "+f"(c[1]), "+f"(c[2]), "+f"(c[3])
        : "r"(a[0]), "r"(a[1]), "r"(a[2]), "r"(a[3]), "r"(b0), "r"(b1));
}
__device__ __forceinline__ void mma_f16(float* c, const unsigned* a, unsigned b0, unsigned b1) {
    asm volatile(
        "mma.sync.aligned.m16n8k16.row.col.f32.f16.f16.f32 "
        "{%0,%1,%2,%3}, {%4,%5,%6,%7}, {%8,%9}, {%0,%1,%2,%3};\n"
        : "+f"(c[0]), "+f"(c[1]), "+f"(c[2]), "+f"(c[3])
        : "r"(a[0]), "r"(a[1]), "r"(a[2]), "r"(a[3]), "r"(b0), "r"(b1));
}

// ---------- packs ----------
__global__ void pack_w1_kernel(const float* __restrict__ W1A, const float* __restrict__ W1S,
                               const float* __restrict__ W1B)
{
    int idx = blockIdx.x * blockDim.x + threadIdx.x;
    if (idx >= 3 * 256 * 1024) return;
    int k = idx & 1023, n = (idx >> 10) & 255, g = idx >> 18;
    const float* W1 = (g == 0) ? W1A : (g == 1) ? W1S : W1B;
    float w = W1[((size_t)(n >> 6) * 1024 + k) * 64 + (n & 63)];
    g_Wp[idx] = __float2half_rn(w);
}
__global__ void pack_w2_kernel(const float* __restrict__ W2A, const float* __restrict__ W2S,
                               const float* __restrict__ W2B)
{
    int idx = blockIdx.x * blockDim.x + threadIdx.x;
    if (idx >= 3 * 4 * 256 * 64) return;
    int k = idx & 63, d = (idx >> 6) & 255, e = (idx >> 14) & 3, g = idx >> 16;
    const float* W2 = (g == 0) ? W2A : (g == 1) ? W2S : W2B;
    float w = W2[((size_t)e * 64 + k) * 256 + d];
    __nv_bfloat16 hi = __float2bfloat16(w);
    g_W2p_hi[idx] = hi;
    g_W2p_lo[idx] = __float2bfloat16(w - __bfloat162float(hi));
}

// ---------- gates ----------
__global__ __launch_bounds__(256)
void gate_kernel(const float* __restrict__ xA, const float* __restrict__ xS,
                 const float* __restrict__ xB,
                 const float* __restrict__ WgA, const float* __restrict__ bgA,
                 const float* __restrict__ WgS, const float* __restrict__ bgS,
                 const float* __restrict__ WgB, const float* __restrict__ bgB)
{
    __shared__ float sWg[12][1024];
    const int g = blockIdx.z;
    const int row0 = blockIdx.x * 64;
    const float* x  = (g == 0) ? xA  : (g == 1) ? xS  : xB;
    const float* Wg = (g == 0) ? WgA : (g == 1) ? WgS : WgB;
    const float* bg = (g == 0) ? bgA : (g == 1) ? bgS : bgB;
    const int G = (g == 1) ? 12 : 8;
    const int tid = threadIdx.x, lane = tid & 31, wid = tid >> 5;

    for (int i = tid; i < 12 * 1024; i += 256) {
        int j = i >> 10, k = i & 1023;
        sWg[j][k] = (j < G) ? Wg[(size_t)k * G + j] : 0.f;
    }
    __syncthreads();

    for (int rp = 0; rp < 4; rp++) {
        int r0 = row0 + wid * 8 + rp * 2;
        float a0[12], a1[12];
        #pragma unroll
        for (int j = 0; j < 12; j++) { a0[j] = 0.f; a1[j] = 0.f; }
        const float* xr0 = x + (size_t)r0 * 1024;
        const float* xr1 = xr0 + 1024;
        for (int k4 = lane * 4; k4 < 1024; k4 += 128) {
            float4 v0 = *reinterpret_cast<const float4*>(xr0 + k4);
            float4 v1 = *reinterpret_cast<const float4*>(xr1 + k4);
            #pragma unroll
            for (int j = 0; j < 12; j++) {
                float4 wv = *reinterpret_cast<const float4*>(&sWg[j][k4]);
                a0[j] += v0.x * wv.x + v0.y * wv.y + v0.z * wv.z + v0.w * wv.w;
                a1[j] += v1.x * wv.x + v1.y * wv.y + v1.z * wv.z + v1.w * wv.w;
            }
        }
        #pragma unroll
        for (int j = 0; j < 12; j++) {
            #pragma unroll
            for (int off = 16; off > 0; off >>= 1) {
                a0[j] += __shfl_xor_sync(0xffffffffu, a0[j], off);
                a1[j] += __shfl_xor_sync(0xffffffffu, a1[j], off);
            }
        }
        if (lane == 0) {
            for (int rr = 0; rr < 2; rr++) {
                float* ac = rr ? a1 : a0;
                float lg[12], m = -1e30f;
                for (int j = 0; j < G; j++) { lg[j] = ac[j] + bg[j]; m = fmaxf(m, lg[j]); }
                float s = 0.f;
                for (int j = 0; j < G; j++) { lg[j] = expf(lg[j] - m); s += lg[j]; }
                float inv = 1.f / s;
                float* dst = g_gates + ((size_t)g * NB + r0 + rr) * 12;
                for (int j = 0; j < G; j++) dst[j] = lg[j] * inv;
            }
        }
    }
}

// ---------- layer 1: fp16 2-term HMMA ----------
#define A_BUF 5120   // 128*40 halves per buffer
#define B_BUF 10240  // 256*40
#define L1_SM 81920  // (2*5120*2 + 2*10240) halves * 2B

__global__ __launch_bounds__(256, 1)
void layer1_kernel(const float* __restrict__ xA, const float* __restrict__ xS,
                   const float* __restrict__ xB,
                   const float* __restrict__ b1A, const float* __restrict__ b1S,
                   const float* __restrict__ b1B)
{
    extern __shared__ __half sm1[];
    __half* sAhi = sm1;              // 2*5120
    __half* sAlo = sm1 + 10240;      // 2*5120
    __half* sB   = sm1 + 20480;      // 2*10240

    const int tid = threadIdx.x;
    const int g = blockIdx.z;
    const int row0 = blockIdx.x * 128;
    const float* x  = (g == 0) ? xA  : (g == 1) ? xS  : xB;
    const float* b1 = (g == 0) ? b1A : (g == 1) ? b1S : b1B;
    const __half* Wp = g_Wp + (size_t)g * 256 * 1024;

    const int lane = tid & 31, wid = tid >> 5;
    const int gid = lane >> 2, quad = lane & 3;
    const int wm = wid & 3, wn = wid >> 2;
    const int a_row = (lane & 7) + ((lane >> 3) & 1) * 8;
    const int a_col = (lane >> 4) * 8;
    const int b_row = (lane & 7) + (lane >> 4) * 8;
    const int b_col = ((lane >> 3) & 1) * 8;

    float acc[2][16][4];
    #pragma unroll
    for (int mt = 0; mt < 2; mt++)
        #pragma unroll
        for (int nt = 0; nt < 16; nt++)
            #pragma unroll
            for (int q = 0; q < 4; q++) acc[mt][nt][q] = 0.f;

    float4 areg[4];
    auto loadA = [&](int kt) {
        int k0 = kt * 32;
        #pragma unroll
        for (int i = 0; i < 4; i++) {
            int idx = tid + i * 256;
            int r = idx >> 3, c = idx & 7;
            areg[i] = *reinterpret_cast<const float4*>(x + (size_t)(row0 + r) * 1024 + k0 + c * 4);
        }
    };
    auto storeA = [&](int buf) {
        #pragma unroll
        for (int i = 0; i < 4; i++) {
            int idx = tid + i * 256;
            int r = idx >> 3, c = idx & 7;
            float4 f = areg[i];
            __half h0 = __float2half_rn(f.x), h1 = __float2half_rn(f.y);
            __half h2 = __float2half_rn(f.z), h3 = __float2half_rn(f.w);
            __half2 H0; H0.x = h0; H0.y = h1;
            __half2 H1; H1.x = h2; H1.y = h3;
            __half2 L0, L1;
            L0.x = __float2half_rn(f.x - __half2float(h0));
            L0.y = __float2half_rn(f.y - __half2float(h1));
            L1.x = __float2half_rn(f.z - __half2float(h2));
            L1.y = __float2half_rn(f.w - __half2float(h3));
            int off = buf * A_BUF + r * 40 + c * 4;
            reinterpret_cast<__half2*>(sAhi + off)[0] = H0;
            reinterpret_cast<__half2*>(sAhi + off)[1] = H1;
            reinterpret_cast<__half2*>(sAlo + off)[0] = L0;
            reinterpret_cast<__half2*>(sAlo + off)[1] = L1;
        }
    };
    auto loadB = [&](int kt, int buf) {
        int k0 = kt * 32;
        #pragma unroll
        for (int i = 0; i < 4; i++) {
            int idx = tid + i * 256;       // 0..1023
            int n = idx >> 2, c = idx & 3;
            cp16(sB + buf * B_BUF + n * 40 + c * 8, Wp + (size_t)n * 1024 + k0 + c * 8);
        }
    };
    auto compute = [&](int buf) {
        const __half* Ah = sAhi + buf * A_BUF;
        const __half* Al = sAlo + buf * A_BUF;
        const __half* Bh = sB + buf * B_BUF;
        #pragma unroll
        for (int ks = 0; ks < 2; ks++) {
            int kb = ks * 16;
            unsigned ah[2][4], al[2][4];
            #pragma unroll
            for (int mt = 0; mt < 2; mt++) {
                int r = wm * 32 + mt * 16 + a_row;
                ldsm4(ah[mt], smem_u32(Ah + r * 40 + kb + a_col));
                ldsm4(al[mt], smem_u32(Al + r * 40 + kb + a_col));
            }
            #pragma unroll
            for (int ntp = 0; ntp < 8; ntp++) {
                int n = wn * 128 + ntp * 16 + b_row;
                unsigned bh[4];
                ldsm4(bh, smem_u32(Bh + n * 40 + kb + b_col));
                #pragma unroll
                for (int mt = 0; mt < 2; mt++) {
                    mma_f16(acc[mt][2 * ntp],     ah[mt], bh[0], bh[1]);
                    mma_f16(acc[mt][2 * ntp],     al[mt], bh[0], bh[1]);
                    mma_f16(acc[mt][2 * ntp + 1], ah[mt], bh[2], bh[3]);
                    mma_f16(acc[mt][2 * ntp + 1], al[mt], bh[2], bh[3]);
                }
            }
        }
    };

    loadA(0);
    loadB(0, 0);
    cp_commit();
    storeA(0);
    cp_wait0();
    __syncthreads();

    #pragma unroll 1
    for (int kt = 0; kt < 32; kt++) {
        int buf = kt & 1;
        if (kt < 31) {
            loadA(kt + 1);
            loadB(kt + 1, buf ^ 1);
            cp_commit();
        }
        compute(buf);
        if (kt < 31) {
            storeA(buf ^ 1);
            cp_wait0();
        }
        __syncthreads();
    }

    __nv_bfloat16* Hhi = g_h_hi + (size_t)g * NB * 256;
    __nv_bfloat16* Hlo = g_h_lo + (size_t)g * NB * 256;
    #pragma unroll
    for (int mt = 0; mt < 2; mt++) {
        #pragma unroll
        for (int nt = 0; nt < 16; nt++) {
            int col = wn * 128 + nt * 8 + quad * 2;
            float2 bv = *reinterpret_cast<const float2*>(b1 + col);
            #pragma unroll
            for (int p = 0; p < 2; p++) {
                int row = row0 + wm * 32 + mt * 16 + gid + p * 8;
                float v0 = fmaxf(acc[mt][nt][p * 2 + 0] + bv.x, 0.f);
                float v1 = fmaxf(acc[mt][nt][p * 2 + 1] + bv.y, 0.f);
                __nv_bfloat16 h0 = __float2bfloat16(v0);
                __nv_bfloat16 h1 = __float2bfloat16(v1);
                __nv_bfloat162 PH; PH.x = h0; PH.y = h1;
                __nv_bfloat162 PL;
                PL.x = __float2bfloat16(v0 - __bfloat162float(h0));
                PL.y = __float2bfloat16(v1 - __bfloat162float(h1));
                size_t base = (size_t)row * 256 + col;
                *reinterpret_cast<__nv_bfloat162*>(Hhi + base) = PH;
                *reinterpret_cast<__nv_bfloat162*>(Hlo + base) = PL;
            }
        }
    }
}

// ---------- layer 2 + combine (bf16 3-term, R7 structure) ----------
#define L2_SH 0
#define L2_SW 36864
#define L2_SG 73728
#define L2_SM 82944
#define L2_STG 18432

__device__ __forceinline__ unsigned ld_u32(const __nv_bfloat16* p) {
    return *reinterpret_cast<const unsigned*>(p);
}

__global__ __launch_bounds__(256, 1)
void layer2_kernel(const float* __restrict__ b2A, const float* __restrict__ b2S,
                   const float* __restrict__ b2B, float* __restrict__ out)
{
    extern __shared__ char sm2[];
    __nv_bfloat16* shb = reinterpret_cast<__nv_bfloat16*>(sm2 + L2_SH);
    __nv_bfloat16* swb = reinterpret_cast<__nv_bfloat16*>(sm2 + L2_SW);
    float* sg = reinterpret_cast<float*>(sm2 + L2_SG);

    const int tid = threadIdx.x;
    const int d0 = blockIdx.x * 64;
    const int row0 = blockIdx.y * 64;
    const int lane = tid & 31, wid = tid >> 5;
    const int gid = lane >> 2, quad = lane & 3;
    const int wm = wid & 1, wn = wid >> 1;

    const int a_row = (lane & 7) + ((lane >> 3) & 1) * 8;
    const int a_col = (lane >> 4) * 8;
    const int b_row = (lane & 7) + (lane >> 4) * 8;
    const int b_col = ((lane >> 3) & 1) * 8;

    for (int i = tid; i < 3 * 64 * 12; i += 256) {
        int gg = i / 768, r = (i / 12) & 63, j = i % 12;
        sg[(gg * 64 + r) * 12 + j] = g_gates[((size_t)gg * NB + row0 + r) * 12 + j];
    }

    auto prefetch = [&](int ge, int s) {
        int g = ge >> 2, e = ge & 3;
        const __nv_bfloat16* Hhi = g_h_hi + (size_t)g * NB * 256;
        const __nv_bfloat16* Hlo = g_h_lo + (size_t)g * NB * 256;
        const __nv_bfloat16* Whi = g_W2p_hi + ((size_t)(g * 4 + e) * 256 + d0) * 64;
        const __nv_bfloat16* Wlo = g_W2p_lo + ((size_t)(g * 4 + e) * 256 + d0) * 64;
        __nv_bfloat16* shs = shb + s * (L2_STG / 2);
        __nv_bfloat16* sws = swb + s * (L2_STG / 2);
        #pragma unroll
        for (int i = 0; i < 2; i++) {
            int idx = tid + i * 256;
            int r = idx >> 3, c = idx & 7;
            cp16(shs + r * 72 + c * 8,        Hhi + (size_t)(row0 + r) * 256 + e * 64 + c * 8);
            cp16(shs + 4608 + r * 72 + c * 8, Hlo + (size_t)(row0 + r) * 256 + e * 64 + c * 8);
            cp16(sws + r * 72 + c * 8,        Whi + (size_t)r * 64 + c * 8);
            cp16(sws + 4608 + r * 72 + c * 8, Wlo + (size_t)r * 64 + c * 8);
        }
        cp_commit();
    };

    float oA[2][2][4], oS[2][2][4], oB[2][2][4];
    #pragma unroll
    for (int mt = 0; mt < 2; mt++)
        #pragma unroll
        for (int nt = 0; nt < 2; nt++)
            #pragma unroll
            for (int q = 0; q < 4; q++) { oA[mt][nt][q] = 0.f; oS[mt][nt][q] = 0.f; oB[mt][nt][q] = 0.f; }

    prefetch(0, 0);
    __syncthreads();

    #pragma unroll 1
    for (int ge = 0; ge < 12; ge++) {
        int s = ge & 1;
        int g = ge >> 2, e = ge & 3;
        if (ge < 11) { prefetch(ge + 1, s ^ 1); cp_wait1(); }
        else cp_wait0();
        __syncthreads();

        const __nv_bfloat16* shs = shb + s * (L2_STG / 2);
        const __nv_bfloat16* sws = swb + s * (L2_STG / 2);

        float t[2][2][4];
        #pragma unroll
        for (int mt = 0; mt < 2; mt++)
            #pragma unroll
            for (int nt = 0; nt < 2; nt++)
                #pragma unroll
                for (int q = 0; q < 4; q++) t[mt][nt][q] = 0.f;

        #pragma unroll
        for (int ks = 0; ks < 4; ks++) {
            int kb = ks * 16;
            unsigned ah[2][4], al[2][4];
            #pragma unroll
            for (int mt = 0; mt < 2; mt++) {
                int r = wm * 32 + mt * 16 + a_row;
                ldsm4(ah[mt], smem_u32(shs + r * 72 + kb + a_col));
                ldsm4(al[mt], smem_u32(shs + 4608 + r * 72 + kb + a_col));
            }
            int n = wn * 16 + b_row;
            unsigned bh[4], bl[4];
            ldsm4(bh, smem_u32(sws + n * 72 + kb + b_col));
            ldsm4(bl, smem_u32(sws + 4608 + n * 72 + kb + b_col));
            #pragma unroll
            for (int mt = 0; mt < 2; mt++) {
                mma_bf16(t[mt][0], ah[mt], bh[0], bh[1]);
                mma_bf16(t[mt][0], ah[mt], bl[0], bl[1]);
                mma_bf16(t[mt][0], al[mt], bh[0], bh[1]);
                mma_bf16(t[mt][1], ah[mt], bh[2], bh[3]);
                mma_bf16(t[mt][1], ah[mt], bl[2], bl[3]);
                mma_bf16(t[mt][1], al[mt], bh[2], bh[3]);
            }
        }

        const float* b2 = (g == 0) ? b2A : (g == 1) ? b2S : b2B;
        #pragma unroll
        for (int mt = 0; mt < 2; mt++) {
            #pragma unroll
            for (int nt = 0; nt < 2; nt++) {
                int col = wn * 16 + nt * 8 + quad * 2;
                float2 bv = *reinterpret_cast<const float2*>(b2 + e * 256 + d0 + col);
                #pragma unroll
                for (int p = 0; p < 2; p++) {
                    int r = wm * 32 + mt * 16 + gid + p * 8;
                    float v0 = fmaxf(t[mt][nt][p * 2 + 0] + bv.x, 0.f);
                    float v1 = fmaxf(t[mt][nt][p * 2 + 1] + bv.y, 0.f);
                    if (g == 0) {
                        float ga = sg[(0 * 64 + r) * 12 + e], gs = sg[(1 * 64 + r) * 12 + e];
                        oA[mt][nt][p * 2 + 0] += ga * v0; oA[mt][nt][p * 2 + 1] += ga * v1;
                        oS[mt][nt][p * 2 + 0] += gs * v0; oS[mt][nt][p * 2 + 1] += gs * v1;
                    } else if (g == 1) {
                        float ga = sg[(0 * 64 + r) * 12 + 4 + e];
                        float gs = sg[(1 * 64 + r) * 12 + 4 + e];
                        float gb = sg[(2 * 64 + r) * 12 + 4 + e];
                        oA[mt][nt][p * 2 + 0] += ga * v0; oA[mt][nt][p * 2 + 1] += ga * v1;
                        oS[mt][nt][p * 2 + 0] += gs * v0; oS[mt][nt][p * 2 + 1] += gs * v1;
                        oB[mt][nt][p * 2 + 0] += gb * v0; oB[mt][nt][p * 2 + 1] += gb * v1;
                    } else {
                        float gs = sg[(1 * 64 + r) * 12 + 8 + e];
                        float gb = sg[(2 * 64 + r) * 12 + e];
                        oS[mt][nt][p * 2 + 0] += gs * v0; oS[mt][nt][p * 2 + 1] += gs * v1;
                        oB[mt][nt][p * 2 + 0] += gb * v0; oB[mt][nt][p * 2 + 1] += gb * v1;
                    }
                }
            }
        }
        __syncthreads();
    }

    #pragma unroll
    for (int mt = 0; mt < 2; mt++) {
        #pragma unroll
        for (int nt = 0; nt < 2; nt++) {
            int col = d0 + wn * 16 + nt * 8 + quad * 2;
            #pragma unroll
            for (int p = 0; p < 2; p++) {
                int row = row0 + wm * 32 + mt * 16 + gid + p * 8;
                size_t base = (size_t)row * 256 + col;
                float2 vA; vA.x = oA[mt][nt][p * 2]; vA.y = oA[mt][nt][p * 2 + 1];
                float2 vS; vS.x = oS[mt][nt][p * 2]; vS.y = oS[mt][nt][p * 2 + 1];
                float2 vB; vB.x = oB[mt][nt][p * 2]; vB.y = oB[mt][nt][p * 2 + 1];
                *reinterpret_cast<float2*>(out + base) = vA;
                *reinterpret_cast<float2*>(out + (size_t)NB * 256 + base) = vS;
                *reinterpret_cast<float2*>(out + 2ull * NB * 256 + base) = vB;
            }
        }
    }
}

extern "C" void kernel_launch(void* const* d_in, const int* in_sizes, int n_in,
                              void* d_out, int out_size)
{
    const float* xA  = (const float*)d_in[0];
    const float* xS  = (const float*)d_in[1];
    const float* xB  = (const float*)d_in[2];
    const float* W1A = (const float*)d_in[3];
    const float* b1A = (const float*)d_in[4];
    const float* W2A = (const float*)d_in[5];
    const float* b2A = (const float*)d_in[6];
    const float* W1S = (const float*)d_in[7];
    const float* b1S = (const float*)d_in[8];
    const float* W2S = (const float*)d_in[9];
    const float* b2S = (const float*)d_in[10];
    const float* W1B = (const float*)d_in[11];
    const float* b1B = (const float*)d_in[12];
    const float* W2B = (const float*)d_in[13];
    const float* b2B = (const float*)d_in[14];
    const float* WgA = (const float*)d_in[15];
    const float* bgA = (const float*)d_in[16];
    const float* WgB = (const float*)d_in[17];
    const float* bgB = (const float*)d_in[18];
    const float* WgS = (const float*)d_in[19];
    const float* bgS = (const float*)d_in[20];
    float* out = (float*)d_out;

    pack_w1_kernel<<<(3 * 256 * 1024 + 255) / 256, 256>>>(W1A, W1S, W1B);
    pack_w2_kernel<<<(3 * 4 * 256 * 64 + 255) / 256, 256>>>(W2A, W2S, W2B);
    gate_kernel<<<dim3(NB / 64, 1, 3), 256>>>(xA, xS, xB, WgA, bgA, WgS, bgS, WgB, bgB);

    cudaFuncSetAttribute(layer1_kernel, cudaFuncAttributeMaxDynamicSharedMemorySize, L1_SM);
    layer1_kernel<<<dim3(NB / 128, 1, 3), 256, L1_SM>>>(xA, xS, xB, b1A, b1S, b1B);

    cudaFuncSetAttribute(layer2_kernel, cudaFuncAttributeMaxDynamicSharedMemorySize, L2_SM);
    layer2_kernel<<<dim3(256 / 64, NB / 64), 256, L2_SM>>>(b2A, b2S, b2B, out);
}

// round 10
// speedup vs baseline: 1.5117x; 1.2169x over previous
#include <cuda_runtime.h>
#include <cuda_bf16.h>
#include <cuda_fp16.h>
#include <cstdint>

#define NB 16384

__device__ __half g_Wp[3 * 256 * 1024];        // W1 fp16
__device__ __half g_W2p[3 * 4 * 256 * 64];     // W2 fp16 [g][e][d][k]
__device__ __half g_h[3ull * NB * 256];        // h fp16
__device__ float  g_gates[3ull * NB * 12];

__device__ __forceinline__ uint32_t smem_u32(const void* p) {
    uint32_t a;
    asm("{ .reg .u64 t; cvta.to.shared.u64 t, %1; cvt.u32.u64 %0, t; }" : "=r"(a) : "l"(p));
    return a;
}
__device__ __forceinline__ void cp16s(uint32_t dst, const void* src) {
    asm volatile("cp.async.cg.shared.global [%0], [%1], 16;\n" :: "r"(dst), "l"(src));
}
__device__ __forceinline__ void cp16(void* dst, const void* src) { cp16s(smem_u32(dst), src); }
__device__ __forceinline__ void cp_commit() { asm volatile("cp.async.commit_group;\n"); }
__device__ __forceinline__ void cp_wait0()  { asm volatile("cp.async.wait_group 0;\n"); }
__device__ __forceinline__ void cp_wait1()  { asm volatile("cp.async.wait_group 1;\n"); }

__device__ __forceinline__ void ldsm4(unsigned* r, uint32_t a) {
    asm volatile("ldmatrix.sync.aligned.m8n8.x4.shared.b16 {%0,%1,%2,%3}, [%4];"
        : "=r"(r[0]), "=r"(r[1]), "=r"(r[2]), "=r"(r[3]) : "r"(a));
}
__device__ __forceinline__ void mma_f16(float* c, const unsigned* a, unsigned b0, unsigned b1) {
    asm volatile(
        "mma.sync.aligned.m16n8k16.row.col.f32.f16.f16.f32 "
        "{%0,%1,%2,%3}, {%4,%5,%6,%7}, {%8,%9}, {%0,%1,%2,%3};\n"
        : "+f"(c[0]), "+f"(c[1]), "+f"(c[2]), "+f"(c[3])
        : "r"(a[0]), "r"(a[1]), "r"(a[2]), "r"(a[3]), "r"(b0), "r"(b1));
}

// ---------- packs ----------
__global__ void pack_w1_kernel(const float* __restrict__ W1A, const float* __restrict__ W1S,
                               const float* __restrict__ W1B)
{
    int idx = blockIdx.x * blockDim.x + threadIdx.x;
    if (idx >= 3 * 256 * 1024) return;
    int k = idx & 1023, n = (idx >> 10) & 255, g = idx >> 18;
    const float* W1 = (g == 0) ? W1A : (g == 1) ? W1S : W1B;
    g_Wp[idx] = __float2half_rn(W1[((size_t)(n >> 6) * 1024 + k) * 64 + (n & 63)]);
}
__global__ void pack_w2_kernel(const float* __restrict__ W2A, const float* __restrict__ W2S,
                               const float* __restrict__ W2B)
{
    int idx = blockIdx.x * blockDim.x + threadIdx.x;
    if (idx >= 3 * 4 * 256 * 64) return;
    int k = idx & 63, d = (idx >> 6) & 255, e = (idx >> 14) & 3, g = idx >> 16;
    const float* W2 = (g == 0) ? W2A : (g == 1) ? W2S : W2B;
    g_W2p[idx] = __float2half_rn(W2[((size_t)e * 64 + k) * 256 + d]);
}

// ---------- gates ----------
__global__ __launch_bounds__(256)
void gate_kernel(const float* __restrict__ xA, const float* __restrict__ xS,
                 const float* __restrict__ xB,
                 const float* __restrict__ WgA, const float* __restrict__ bgA,
                 const float* __restrict__ WgS, const float* __restrict__ bgS,
                 const float* __restrict__ WgB, const float* __restrict__ bgB)
{
    __shared__ float sWg[12][1024];
    const int g = blockIdx.z;
    const int row0 = blockIdx.x * 64;
    const float* x  = (g == 0) ? xA  : (g == 1) ? xS  : xB;
    const float* Wg = (g == 0) ? WgA : (g == 1) ? WgS : WgB;
    const float* bg = (g == 0) ? bgA : (g == 1) ? bgS : bgB;
    const int G = (g == 1) ? 12 : 8;
    const int tid = threadIdx.x, lane = tid & 31, wid = tid >> 5;

    for (int i = tid; i < 12 * 1024; i += 256) {
        int j = i >> 10, k = i & 1023;
        sWg[j][k] = (j < G) ? Wg[(size_t)k * G + j] : 0.f;
    }
    __syncthreads();

    for (int rp = 0; rp < 4; rp++) {
        int r0 = row0 + wid * 8 + rp * 2;
        float a0[12], a1[12];
        #pragma unroll
        for (int j = 0; j < 12; j++) { a0[j] = 0.f; a1[j] = 0.f; }
        const float* xr0 = x + (size_t)r0 * 1024;
        const float* xr1 = xr0 + 1024;
        for (int k4 = lane * 4; k4 < 1024; k4 += 128) {
            float4 v0 = *reinterpret_cast<const float4*>(xr0 + k4);
            float4 v1 = *reinterpret_cast<const float4*>(xr1 + k4);
            #pragma unroll
            for (int j = 0; j < 12; j++) {
                float4 wv = *reinterpret_cast<const float4*>(&sWg[j][k4]);
                a0[j] += v0.x * wv.x + v0.y * wv.y + v0.z * wv.z + v0.w * wv.w;
                a1[j] += v1.x * wv.x + v1.y * wv.y + v1.z * wv.z + v1.w * wv.w;
            }
        }
        #pragma unroll
        for (int j = 0; j < 12; j++) {
            #pragma unroll
            for (int off = 16; off > 0; off >>= 1) {
                a0[j] += __shfl_xor_sync(0xffffffffu, a0[j], off);
                a1[j] += __shfl_xor_sync(0xffffffffu, a1[j], off);
            }
        }
        if (lane == 0) {
            for (int rr = 0; rr < 2; rr++) {
                float* ac = rr ? a1 : a0;
                float lg[12], m = -1e30f;
                for (int j = 0; j < G; j++) { lg[j] = ac[j] + bg[j]; m = fmaxf(m, lg[j]); }
                float s = 0.f;
                for (int j = 0; j < G; j++) { lg[j] = expf(lg[j] - m); s += lg[j]; }
                float inv = 1.f / s;
                float* dst = g_gates + ((size_t)g * NB + r0 + rr) * 12;
                for (int j = 0; j < G; j++) dst[j] = lg[j] * inv;
            }
        }
    }
}

// ---------- layer 1: fp16 2-term HMMA, BM=128 BN=128, 2 CTAs/SM ----------
#define A_BUF 5120   // 128*40 halves
#define B_BUF1 5120  // 128*40 halves
#define L1_SM 61440  // (2*5120*2 + 2*5120) * 2B

__global__ __launch_bounds__(256, 2)
void layer1_kernel(const float* __restrict__ xA, const float* __restrict__ xS,
                   const float* __restrict__ xB,
                   const float* __restrict__ b1A, const float* __restrict__ b1S,
                   const float* __restrict__ b1B)
{
    extern __shared__ __half sm1[];
    __half* sAhi = sm1;              // 2*5120
    __half* sAlo = sm1 + 10240;      // 2*5120
    __half* sB   = sm1 + 20480;      // 2*5120

    const int tid = threadIdx.x;
    const int g = blockIdx.z;
    const int nb = blockIdx.y;       // N-block: 0 or 1
    const int row0 = blockIdx.x * 128;
    const float* x  = (g == 0) ? xA  : (g == 1) ? xS  : xB;
    const float* b1 = ((g == 0) ? b1A : (g == 1) ? b1S : b1B) + nb * 128;
    const __half* Wp = g_Wp + (size_t)g * 256 * 1024 + (size_t)nb * 128 * 1024;

    const int lane = tid & 31, wid = tid >> 5;
    const int gid = lane >> 2, quad = lane & 3;
    const int wm = wid & 3, wn = wid >> 2;   // 4 x M32, 2 x N64
    const int a_row = (lane & 7) + ((lane >> 3) & 1) * 8;
    const int a_col = (lane >> 4) * 8;
    const int b_row = (lane & 7) + (lane >> 4) * 8;
    const int b_col = ((lane >> 3) & 1) * 8;

    float acc[2][8][4];
    #pragma unroll
    for (int mt = 0; mt < 2; mt++)
        #pragma unroll
        for (int nt = 0; nt < 8; nt++)
            #pragma unroll
            for (int q = 0; q < 4; q++) acc[mt][nt][q] = 0.f;

    float4 areg[4];
    auto loadA = [&](int kt) {
        int k0 = kt * 32;
        #pragma unroll
        for (int i = 0; i < 4; i++) {
            int idx = tid + i * 256;
            int r = idx >> 3, c = idx & 7;
            areg[i] = *reinterpret_cast<const float4*>(x + (size_t)(row0 + r) * 1024 + k0 + c * 4);
        }
    };
    auto storeA = [&](int buf) {
        #pragma unroll
        for (int i = 0; i < 4; i++) {
            int idx = tid + i * 256;
            int r = idx >> 3, c = idx & 7;
            float4 f = areg[i];
            __half h0 = __float2half_rn(f.x), h1 = __float2half_rn(f.y);
            __half h2 = __float2half_rn(f.z), h3 = __float2half_rn(f.w);
            __half2 H0; H0.x = h0; H0.y = h1;
            __half2 H1; H1.x = h2; H1.y = h3;
            __half2 L0, L1;
            L0.x = __float2half_rn(f.x - __half2float(h0));
            L0.y = __float2half_rn(f.y - __half2float(h1));
            L1.x = __float2half_rn(f.z - __half2float(h2));
            L1.y = __float2half_rn(f.w - __half2float(h3));
            int off = buf * A_BUF + r * 40 + c * 4;
            reinterpret_cast<__half2*>(sAhi + off)[0] = H0;
            reinterpret_cast<__half2*>(sAhi + off)[1] = H1;
            reinterpret_cast<__half2*>(sAlo + off)[0] = L0;
            reinterpret_cast<__half2*>(sAlo + off)[1] = L1;
        }
    };
    auto loadB = [&](int kt, int buf) {
        int k0 = kt * 32;
        #pragma unroll
        for (int i = 0; i < 2; i++) {
            int idx = tid + i * 256;       // 0..511
            int n = idx >> 2, c = idx & 3;
            cp16(sB + buf * B_BUF1 + n * 40 + c * 8, Wp + (size_t)n * 1024 + k0 + c * 8);
        }
    };
    auto compute = [&](int buf) {
        const __half* Ah = sAhi + buf * A_BUF;
        const __half* Al = sAlo + buf * A_BUF;
        const __half* Bh = sB + buf * B_BUF1;
        #pragma unroll
        for (int ks = 0; ks < 2; ks++) {
            int kb = ks * 16;
            unsigned ah[2][4], al[2][4];
            #pragma unroll
            for (int mt = 0; mt < 2; mt++) {
                int r = wm * 32 + mt * 16 + a_row;
                ldsm4(ah[mt], smem_u32(Ah + r * 40 + kb + a_col));
                ldsm4(al[mt], smem_u32(Al + r * 40 + kb + a_col));
            }
            #pragma unroll
            for (int ntp = 0; ntp < 4; ntp++) {
                int n = wn * 64 + ntp * 16 + b_row;
                unsigned bh[4];
                ldsm4(bh, smem_u32(Bh + n * 40 + kb + b_col));
                #pragma unroll
                for (int mt = 0; mt < 2; mt++) {
                    mma_f16(acc[mt][2 * ntp],     ah[mt], bh[0], bh[1]);
                    mma_f16(acc[mt][2 * ntp],     al[mt], bh[0], bh[1]);
                    mma_f16(acc[mt][2 * ntp + 1], ah[mt], bh[2], bh[3]);
                    mma_f16(acc[mt][2 * ntp + 1], al[mt], bh[2], bh[3]);
                }
            }
        }
    };

    loadA(0);
    loadB(0, 0);
    cp_commit();
    storeA(0);
    cp_wait0();
    __syncthreads();

    #pragma unroll 1
    for (int kt = 0; kt < 32; kt++) {
        int buf = kt & 1;
        if (kt < 31) {
            loadA(kt + 1);
            loadB(kt + 1, buf ^ 1);
            cp_commit();
        }
        compute(buf);
        if (kt < 31) {
            storeA(buf ^ 1);
            cp_wait0();
        }
        __syncthreads();
    }

    __half* Hp = g_h + (size_t)g * NB * 256;
    #pragma unroll
    for (int mt = 0; mt < 2; mt++) {
        #pragma unroll
        for (int nt = 0; nt < 8; nt++) {
            int col = wn * 64 + nt * 8 + quad * 2;
            float2 bv = *reinterpret_cast<const float2*>(b1 + col);
            #pragma unroll
            for (int p = 0; p < 2; p++) {
                int row = row0 + wm * 32 + mt * 16 + gid + p * 8;
                float v0 = fmaxf(acc[mt][nt][p * 2 + 0] + bv.x, 0.f);
                float v1 = fmaxf(acc[mt][nt][p * 2 + 1] + bv.y, 0.f);
                __half2 PH; PH.x = __float2half_rn(v0); PH.y = __float2half_rn(v1);
                *reinterpret_cast<__half2*>(Hp + (size_t)row * 256 + nb * 128 + col) = PH;
            }
        }
    }
}

// ---------- layer 2 + combine: fp16 1-term ----------
// smem halves: shb 2x4608, swb 2x4608; sg floats at 36864B
#define L2_SM 46080

__global__ __launch_bounds__(256, 1)
void layer2_kernel(const float* __restrict__ b2A, const float* __restrict__ b2S,
                   const float* __restrict__ b2B, float* __restrict__ out)
{
    extern __shared__ char sm2[];
    __half* shb = reinterpret_cast<__half*>(sm2);            // 2 stages x 4608
    __half* swb = reinterpret_cast<__half*>(sm2 + 18432);    // 2 stages x 4608
    float* sg = reinterpret_cast<float*>(sm2 + 36864);       // [3][64][12]

    const int tid = threadIdx.x;
    const int d0 = blockIdx.x * 64;
    const int row0 = blockIdx.y * 64;
    const int lane = tid & 31, wid = tid >> 5;
    const int gid = lane >> 2, quad = lane & 3;
    const int wm = wid & 1, wn = wid >> 1;

    const int a_row = (lane & 7) + ((lane >> 3) & 1) * 8;
    const int a_col = (lane >> 4) * 8;
    const int b_row = (lane & 7) + (lane >> 4) * 8;
    const int b_col = ((lane >> 3) & 1) * 8;

    for (int i = tid; i < 3 * 64 * 12; i += 256) {
        int gg = i / 768, r = (i / 12) & 63, j = i % 12;
        sg[(gg * 64 + r) * 12 + j] = g_gates[((size_t)gg * NB + row0 + r) * 12 + j];
    }

    auto prefetch = [&](int ge, int s) {
        int g = ge >> 2, e = ge & 3;
        const __half* Hp = g_h + (size_t)g * NB * 256;
        const __half* Wp2 = g_W2p + ((size_t)(g * 4 + e) * 256 + d0) * 64;
        __half* shs = shb + s * 4608;
        __half* sws = swb + s * 4608;
        #pragma unroll
        for (int i = 0; i < 2; i++) {
            int idx = tid + i * 256;
            int r = idx >> 3, c = idx & 7;
            cp16(shs + r * 72 + c * 8, Hp + (size_t)(row0 + r) * 256 + e * 64 + c * 8);
            cp16(sws + r * 72 + c * 8, Wp2 + (size_t)r * 64 + c * 8);
        }
        cp_commit();
    };

    float oA[2][2][4], oS[2][2][4], oB[2][2][4];
    #pragma unroll
    for (int mt = 0; mt < 2; mt++)
        #pragma unroll
        for (int nt = 0; nt < 2; nt++)
            #pragma unroll
            for (int q = 0; q < 4; q++) { oA[mt][nt][q] = 0.f; oS[mt][nt][q] = 0.f; oB[mt][nt][q] = 0.f; }

    prefetch(0, 0);
    __syncthreads();

    #pragma unroll 1
    for (int ge = 0; ge < 12; ge++) {
        int s = ge & 1;
        int g = ge >> 2, e = ge & 3;
        if (ge < 11) { prefetch(ge + 1, s ^ 1); cp_wait1(); }
        else cp_wait0();
        __syncthreads();

        const __half* shs = shb + s * 4608;
        const __half* sws = swb + s * 4608;

        float t[2][2][4];
        #pragma unroll
        for (int mt = 0; mt < 2; mt++)
            #pragma unroll
            for (int nt = 0; nt < 2; nt++)
                #pragma unroll
                for (int q = 0; q < 4; q++) t[mt][nt][q] = 0.f;

        #pragma unroll
        for (int ks = 0; ks < 4; ks++) {
            int kb = ks * 16;
            unsigned ah[2][4];
            #pragma unroll
            for (int mt = 0; mt < 2; mt++) {
                int r = wm * 32 + mt * 16 + a_row;
                ldsm4(ah[mt], smem_u32(shs + r * 72 + kb + a_col));
            }
            int n = wn * 16 + b_row;
            unsigned bh[4];
            ldsm4(bh, smem_u32(sws + n * 72 + kb + b_col));
            #pragma unroll
            for (int mt = 0; mt < 2; mt++) {
                mma_f16(t[mt][0], ah[mt], bh[0], bh[1]);
                mma_f16(t[mt][1], ah[mt], bh[2], bh[3]);
            }
        }

        const float* b2 = (g == 0) ? b2A : (g == 1) ? b2S : b2B;
        #pragma unroll
        for (int mt = 0; mt < 2; mt++) {
            #pragma unroll
            for (int nt = 0; nt < 2; nt++) {
                int col = wn * 16 + nt * 8 + quad * 2;
                float2 bv = *reinterpret_cast<const float2*>(b2 + e * 256 + d0 + col);
                #pragma unroll
                for (int p = 0; p < 2; p++) {
                    int r = wm * 32 + mt * 16 + gid + p * 8;
                    float v0 = fmaxf(t[mt][nt][p * 2 + 0] + bv.x, 0.f);
                    float v1 = fmaxf(t[mt][nt][p * 2 + 1] + bv.y, 0.f);
                    if (g == 0) {
                        float ga = sg[(0 * 64 + r) * 12 + e], gs = sg[(1 * 64 + r) * 12 + e];
                        oA[mt][nt][p * 2 + 0] += ga * v0; oA[mt][nt][p * 2 + 1] += ga * v1;
                        oS[mt][nt][p * 2 + 0] += gs * v0; oS[mt][nt][p * 2 + 1] += gs * v1;
                    } else if (g == 1) {
                        float ga = sg[(0 * 64 + r) * 12 + 4 + e];
                        float gs = sg[(1 * 64 + r) * 12 + 4 + e];
                        float gb = sg[(2 * 64 + r) * 12 + 4 + e];
                        oA[mt][nt][p * 2 + 0] += ga * v0; oA[mt][nt][p * 2 + 1] += ga * v1;
                        oS[mt][nt][p * 2 + 0] += gs * v0; oS[mt][nt][p * 2 + 1] += gs * v1;
                        oB[mt][nt][p * 2 + 0] += gb * v0; oB[mt][nt][p * 2 + 1] += gb * v1;
                    } else {
                        float gs = sg[(1 * 64 + r) * 12 + 8 + e];
                        float gb = sg[(2 * 64 + r) * 12 + e];
                        oS[mt][nt][p * 2 + 0] += gs * v0; oS[mt][nt][p * 2 + 1] += gs * v1;
                        oB[mt][nt][p * 2 + 0] += gb * v0; oB[mt][nt][p * 2 + 1] += gb * v1;
                    }
                }
            }
        }
        __syncthreads();
    }

    #pragma unroll
    for (int mt = 0; mt < 2; mt++) {
        #pragma unroll
        for (int nt = 0; nt < 2; nt++) {
            int col = d0 + wn * 16 + nt * 8 + quad * 2;
            #pragma unroll
            for (int p = 0; p < 2; p++) {
                int row = row0 + wm * 32 + mt * 16 + gid + p * 8;
                size_t base = (size_t)row * 256 + col;
                float2 vA; vA.x = oA[mt][nt][p * 2]; vA.y = oA[mt][nt][p * 2 + 1];
                float2 vS; vS.x = oS[mt][nt][p * 2]; vS.y = oS[mt][nt][p * 2 + 1];
                float2 vB; vB.x = oB[mt][nt][p * 2]; vB.y = oB[mt][nt][p * 2 + 1];
                *reinterpret_cast<float2*>(out + base) = vA;
                *reinterpret_cast<float2*>(out + (size_t)NB * 256 + base) = vS;
                *reinterpret_cast<float2*>(out + 2ull * NB * 256 + base) = vB;
            }
        }
    }
}

extern "C" void kernel_launch(void* const* d_in, const int* in_sizes, int n_in,
                              void* d_out, int out_size)
{
    const float* xA  = (const float*)d_in[0];
    const float* xS  = (const float*)d_in[1];
    const float* xB  = (const float*)d_in[2];
    const float* W1A = (const float*)d_in[3];
    const float* b1A = (const float*)d_in[4];
    const float* W2A = (const float*)d_in[5];
    const float* b2A = (const float*)d_in[6];
    const float* W1S = (const float*)d_in[7];
    const float* b1S = (const float*)d_in[8];
    const float* W2S = (const float*)d_in[9];
    const float* b2S = (const float*)d_in[10];
    const float* W1B = (const float*)d_in[11];
    const float* b1B = (const float*)d_in[12];
    const float* W2B = (const float*)d_in[13];
    const float* b2B = (const float*)d_in[14];
    const float* WgA = (const float*)d_in[15];
    const float* bgA = (const float*)d_in[16];
    const float* WgB = (const float*)d_in[17];
    const float* bgB = (const float*)d_in[18];
    const float* WgS = (const float*)d_in[19];
    const float* bgS = (const float*)d_in[20];
    float* out = (float*)d_out;

    pack_w1_kernel<<<(3 * 256 * 1024 + 255) / 256, 256>>>(W1A, W1S, W1B);
    pack_w2_kernel<<<(3 * 4 * 256 * 64 + 255) / 256, 256>>>(W2A, W2S, W2B);
    gate_kernel<<<dim3(NB / 64, 1, 3), 256>>>(xA, xS, xB, WgA, bgA, WgS, bgS, WgB, bgB);

    cudaFuncSetAttribute(layer1_kernel, cudaFuncAttributeMaxDynamicSharedMemorySize, L1_SM);
    layer1_kernel<<<dim3(NB / 128, 2, 3), 256, L1_SM>>>(xA, xS, xB, b1A, b1S, b1B);

    cudaFuncSetAttribute(layer2_kernel, cudaFuncAttributeMaxDynamicSharedMemorySize, L2_SM);
    layer2_kernel<<<dim3(256 / 64, NB / 64), 256, L2_SM>>>(b2A, b2S, b2B, out);
}

// round 11
// speedup vs baseline: 2.4323x; 1.6090x over previous
#include <cuda_runtime.h>
#include <cuda_bf16.h>
#include <cuda_fp16.h>
#include <cstdint>

#define NB 16384

__device__ __half g_W1cat[3 * 288 * 1024];     // [g][n:288][k] fp16; n<256 W1, 256+ Wg (zero-pad)
__device__ __half g_W2p[3 * 4 * 256 * 64];     // W2 fp16 [g][e][d][k]
__device__ __half g_h[3ull * NB * 256];        // h fp16
__device__ float  g_gates[3ull * NB * 12];

__device__ __forceinline__ uint32_t smem_u32(const void* p) {
    uint32_t a;
    asm("{ .reg .u64 t; cvta.to.shared.u64 t, %1; cvt.u32.u64 %0, t; }" : "=r"(a) : "l"(p));
    return a;
}
__device__ __forceinline__ void cp16s(uint32_t dst, const void* src) {
    asm volatile("cp.async.cg.shared.global [%0], [%1], 16;\n" :: "r"(dst), "l"(src));
}
__device__ __forceinline__ void cp16(void* dst, const void* src) { cp16s(smem_u32(dst), src); }
__device__ __forceinline__ void cp_commit() { asm volatile("cp.async.commit_group;\n"); }
__device__ __forceinline__ void cp_wait0()  { asm volatile("cp.async.wait_group 0;\n"); }
__device__ __forceinline__ void cp_wait1()  { asm volatile("cp.async.wait_group 1;\n"); }

__device__ __forceinline__ void ldsm4(unsigned* r, uint32_t a) {
    asm volatile("ldmatrix.sync.aligned.m8n8.x4.shared.b16 {%0,%1,%2,%3}, [%4];"
        : "=r"(r[0]), "=r"(r[1]), "=r"(r[2]), "=r"(r[3]) : "r"(a));
}
__device__ __forceinline__ void mma_f16(float* c, const unsigned* a, unsigned b0, unsigned b1) {
    asm volatile(
        "mma.sync.aligned.m16n8k16.row.col.f32.f16.f16.f32 "
        "{%0,%1,%2,%3}, {%4,%5,%6,%7}, {%8,%9}, {%0,%1,%2,%3};\n"
        : "+f"(c[0]), "+f"(c[1]), "+f"(c[2]), "+f"(c[3])
        : "r"(a[0]), "r"(a[1]), "r"(a[2]), "r"(a[3]), "r"(b0), "r"(b1));
}

// ---------- packs ----------
__global__ void pack_w1_kernel(const float* __restrict__ W1A, const float* __restrict__ W1S,
                               const float* __restrict__ W1B,
                               const float* __restrict__ WgA, const float* __restrict__ WgS,
                               const float* __restrict__ WgB)
{
    int idx = blockIdx.x * blockDim.x + threadIdx.x;
    if (idx >= 3 * 288 * 1024) return;
    int k = idx & 1023;
    int n = (idx >> 10) % 288;
    int g = idx / (288 * 1024);
    const float* W1 = (g == 0) ? W1A : (g == 1) ? W1S : W1B;
    const float* Wg = (g == 0) ? WgA : (g == 1) ? WgS : WgB;
    int G = (g == 1) ? 12 : 8;
    float w = 0.f;
    if (n < 256)            w = W1[((size_t)(n >> 6) * 1024 + k) * 64 + (n & 63)];
    else if (n < 256 + G)   w = Wg[(size_t)k * G + (n - 256)];
    g_W1cat[idx] = __float2half_rn(w);
}
__global__ void pack_w2_kernel(const float* __restrict__ W2A, const float* __restrict__ W2S,
                               const float* __restrict__ W2B)
{
    int idx = blockIdx.x * blockDim.x + threadIdx.x;
    if (idx >= 3 * 4 * 256 * 64) return;
    int k = idx & 63, d = (idx >> 6) & 255, e = (idx >> 14) & 3, g = idx >> 16;
    const float* W2 = (g == 0) ? W2A : (g == 1) ? W2S : W2B;
    g_W2p[idx] = __float2half_rn(W2[((size_t)e * 64 + k) * 256 + d]);
}

// ---------- layer 1 + gate: fp16 1-term HMMA, BM=128 BN=288 ----------
#define A_BUF 5120    // 128*40 halves
#define B_BUF 11520   // 288*40 halves
#define L1_SM 66560   // (2*5120 + 2*11520)*2

__global__ __launch_bounds__(256, 1)
void layer1_kernel(const float* __restrict__ xA, const float* __restrict__ xS,
                   const float* __restrict__ xB,
                   const float* __restrict__ b1A, const float* __restrict__ b1S,
                   const float* __restrict__ b1B,
                   const float* __restrict__ bgA, const float* __restrict__ bgS,
                   const float* __restrict__ bgB)
{
    extern __shared__ __half sm1[];
    __half* sA = sm1;                // 2 x 5120
    __half* sB = sm1 + 10240;        // 2 x 11520

    const int tid = threadIdx.x;
    const int g = blockIdx.z;
    const int row0 = blockIdx.x * 128;
    const float* x  = (g == 0) ? xA  : (g == 1) ? xS  : xB;
    const float* b1 = (g == 0) ? b1A : (g == 1) ? b1S : b1B;
    const float* bg = (g == 0) ? bgA : (g == 1) ? bgS : bgB;
    const int G = (g == 1) ? 12 : 8;
    const __half* Wp = g_W1cat + (size_t)g * 288 * 1024;

    const int lane = tid & 31, wid = tid >> 5;
    const int gid = lane >> 2, quad = lane & 3;
    const int wm = wid & 3, wn = wid >> 2;   // 4 x M32, 2 x N144
    const int a_row = (lane & 7) + ((lane >> 3) & 1) * 8;
    const int a_col = (lane >> 4) * 8;
    const int b_row = (lane & 7) + (lane >> 4) * 8;
    const int b_col = ((lane >> 3) & 1) * 8;

    float acc[2][18][4];
    #pragma unroll
    for (int mt = 0; mt < 2; mt++)
        #pragma unroll
        for (int nt = 0; nt < 18; nt++)
            #pragma unroll
            for (int q = 0; q < 4; q++) acc[mt][nt][q] = 0.f;

    float4 areg[4];
    auto loadA = [&](int kt) {
        int k0 = kt * 32;
        #pragma unroll
        for (int i = 0; i < 4; i++) {
            int idx = tid + i * 256;
            int r = idx >> 3, c = idx & 7;
            areg[i] = *reinterpret_cast<const float4*>(x + (size_t)(row0 + r) * 1024 + k0 + c * 4);
        }
    };
    auto storeA = [&](int buf) {
        #pragma unroll
        for (int i = 0; i < 4; i++) {
            int idx = tid + i * 256;
            int r = idx >> 3, c = idx & 7;
            float4 f = areg[i];
            __half2 H0; H0.x = __float2half_rn(f.x); H0.y = __float2half_rn(f.y);
            __half2 H1; H1.x = __float2half_rn(f.z); H1.y = __float2half_rn(f.w);
            int off = buf * A_BUF + r * 40 + c * 4;
            reinterpret_cast<__half2*>(sA + off)[0] = H0;
            reinterpret_cast<__half2*>(sA + off)[1] = H1;
        }
    };
    auto loadB = [&](int kt, int buf) {
        int k0 = kt * 32;
        #pragma unroll
        for (int i = 0; i < 5; i++) {
            int idx = tid + i * 256;     // 0..1151 (288*4)
            if (idx < 1152) {
                int n = idx >> 2, c = idx & 3;
                cp16(sB + buf * B_BUF + n * 40 + c * 8, Wp + (size_t)n * 1024 + k0 + c * 8);
            }
        }
    };
    auto compute = [&](int buf) {
        const __half* Ah = sA + buf * A_BUF;
        const __half* Bh = sB + buf * B_BUF;
        #pragma unroll
        for (int ks = 0; ks < 2; ks++) {
            int kb = ks * 16;
            unsigned ah[2][4];
            #pragma unroll
            for (int mt = 0; mt < 2; mt++) {
                int r = wm * 32 + mt * 16 + a_row;
                ldsm4(ah[mt], smem_u32(Ah + r * 40 + kb + a_col));
            }
            #pragma unroll
            for (int ntp = 0; ntp < 9; ntp++) {
                int n = wn * 144 + ntp * 16 + b_row;
                unsigned bh[4];
                ldsm4(bh, smem_u32(Bh + n * 40 + kb + b_col));
                #pragma unroll
                for (int mt = 0; mt < 2; mt++) {
                    mma_f16(acc[mt][2 * ntp],     ah[mt], bh[0], bh[1]);
                    mma_f16(acc[mt][2 * ntp + 1], ah[mt], bh[2], bh[3]);
                }
            }
        }
    };

    loadA(0);
    loadB(0, 0);
    cp_commit();
    storeA(0);
    cp_wait0();
    __syncthreads();

    #pragma unroll 1
    for (int kt = 0; kt < 32; kt++) {
        int buf = kt & 1;
        if (kt < 31) {
            loadA(kt + 1);
            loadB(kt + 1, buf ^ 1);
            cp_commit();
        }
        compute(buf);
        if (kt < 31) {
            storeA(buf ^ 1);
            cp_wait0();
        }
        __syncthreads();
    }

    // epilogue 1: h (cols < 256) -> fp16 store with bias+relu
    __half* Hp = g_h + (size_t)g * NB * 256;
    #pragma unroll
    for (int mt = 0; mt < 2; mt++) {
        #pragma unroll
        for (int nt = 0; nt < 18; nt++) {
            int col = wn * 144 + nt * 8 + quad * 2;
            if (col < 256) {
                float2 bv = *reinterpret_cast<const float2*>(b1 + col);
                #pragma unroll
                for (int p = 0; p < 2; p++) {
                    int row = row0 + wm * 32 + mt * 16 + gid + p * 8;
                    float v0 = fmaxf(acc[mt][nt][p * 2 + 0] + bv.x, 0.f);
                    float v1 = fmaxf(acc[mt][nt][p * 2 + 1] + bv.y, 0.f);
                    __half2 PH; PH.x = __float2half_rn(v0); PH.y = __float2half_rn(v1);
                    *reinterpret_cast<__half2*>(Hp + (size_t)row * 256 + col) = PH;
                }
            }
        }
    }

    // epilogue 2: gate logits (cols 256..287, held by wn==1, nt 14..17) -> smem -> softmax
    __syncthreads();
    float* slog = reinterpret_cast<float*>(sm1);   // [128][33]
    if (wn == 1) {
        #pragma unroll
        for (int mt = 0; mt < 2; mt++) {
            #pragma unroll
            for (int nt = 14; nt < 18; nt++) {
                int c = nt * 8 - 112 + quad * 2;   // 0..31
                #pragma unroll
                for (int p = 0; p < 2; p++) {
                    int rl = wm * 32 + mt * 16 + gid + p * 8;
                    slog[rl * 33 + c]     = acc[mt][nt][p * 2 + 0];
                    slog[rl * 33 + c + 1] = acc[mt][nt][p * 2 + 1];
                }
            }
        }
    }
    __syncthreads();
    if (tid < 128) {
        float lg[12], m = -1e30f;
        for (int j = 0; j < G; j++) { lg[j] = slog[tid * 33 + j] + bg[j]; m = fmaxf(m, lg[j]); }
        float s = 0.f;
        for (int j = 0; j < G; j++) { lg[j] = expf(lg[j] - m); s += lg[j]; }
        float inv = 1.f / s;
        float* dst = g_gates + ((size_t)g * NB + row0 + tid) * 12;
        for (int j = 0; j < G; j++) dst[j] = lg[j] * inv;
    }
}

// ---------- layer 2 + combine: fp16 1-term (unchanged from R10) ----------
#define L2_SM 46080

__global__ __launch_bounds__(256, 1)
void layer2_kernel(const float* __restrict__ b2A, const float* __restrict__ b2S,
                   const float* __restrict__ b2B, float* __restrict__ out)
{
    extern __shared__ char sm2[];
    __half* shb = reinterpret_cast<__half*>(sm2);
    __half* swb = reinterpret_cast<__half*>(sm2 + 18432);
    float* sg = reinterpret_cast<float*>(sm2 + 36864);

    const int tid = threadIdx.x;
    const int d0 = blockIdx.x * 64;
    const int row0 = blockIdx.y * 64;
    const int lane = tid & 31, wid = tid >> 5;
    const int gid = lane >> 2, quad = lane & 3;
    const int wm = wid & 1, wn = wid >> 1;

    const int a_row = (lane & 7) + ((lane >> 3) & 1) * 8;
    const int a_col = (lane >> 4) * 8;
    const int b_row = (lane & 7) + (lane >> 4) * 8;
    const int b_col = ((lane >> 3) & 1) * 8;

    for (int i = tid; i < 3 * 64 * 12; i += 256) {
        int gg = i / 768, r = (i / 12) & 63, j = i % 12;
        sg[(gg * 64 + r) * 12 + j] = g_gates[((size_t)gg * NB + row0 + r) * 12 + j];
    }

    auto prefetch = [&](int ge, int s) {
        int g = ge >> 2, e = ge & 3;
        const __half* Hp = g_h + (size_t)g * NB * 256;
        const __half* Wp2 = g_W2p + ((size_t)(g * 4 + e) * 256 + d0) * 64;
        __half* shs = shb + s * 4608;
        __half* sws = swb + s * 4608;
        #pragma unroll
        for (int i = 0; i < 2; i++) {
            int idx = tid + i * 256;
            int r = idx >> 3, c = idx & 7;
            cp16(shs + r * 72 + c * 8, Hp + (size_t)(row0 + r) * 256 + e * 64 + c * 8);
            cp16(sws + r * 72 + c * 8, Wp2 + (size_t)r * 64 + c * 8);
        }
        cp_commit();
    };

    float oA[2][2][4], oS[2][2][4], oB[2][2][4];
    #pragma unroll
    for (int mt = 0; mt < 2; mt++)
        #pragma unroll
        for (int nt = 0; nt < 2; nt++)
            #pragma unroll
            for (int q = 0; q < 4; q++) { oA[mt][nt][q] = 0.f; oS[mt][nt][q] = 0.f; oB[mt][nt][q] = 0.f; }

    prefetch(0, 0);
    __syncthreads();

    #pragma unroll 1
    for (int ge = 0; ge < 12; ge++) {
        int s = ge & 1;
        int g = ge >> 2, e = ge & 3;
        if (ge < 11) { prefetch(ge + 1, s ^ 1); cp_wait1(); }
        else cp_wait0();
        __syncthreads();

        const __half* shs = shb + s * 4608;
        const __half* sws = swb + s * 4608;

        float t[2][2][4];
        #pragma unroll
        for (int mt = 0; mt < 2; mt++)
            #pragma unroll
            for (int nt = 0; nt < 2; nt++)
                #pragma unroll
                for (int q = 0; q < 4; q++) t[mt][nt][q] = 0.f;

        #pragma unroll
        for (int ks = 0; ks < 4; ks++) {
            int kb = ks * 16;
            unsigned ah[2][4];
            #pragma unroll
            for (int mt = 0; mt < 2; mt++) {
                int r = wm * 32 + mt * 16 + a_row;
                ldsm4(ah[mt], smem_u32(shs + r * 72 + kb + a_col));
            }
            int n = wn * 16 + b_row;
            unsigned bh[4];
            ldsm4(bh, smem_u32(sws + n * 72 + kb + b_col));
            #pragma unroll
            for (int mt = 0; mt < 2; mt++) {
                mma_f16(t[mt][0], ah[mt], bh[0], bh[1]);
                mma_f16(t[mt][1], ah[mt], bh[2], bh[3]);
            }
        }

        const float* b2 = (g == 0) ? b2A : (g == 1) ? b2S : b2B;
        #pragma unroll
        for (int mt = 0; mt < 2; mt++) {
            #pragma unroll
            for (int nt = 0; nt < 2; nt++) {
                int col = wn * 16 + nt * 8 + quad * 2;
                float2 bv = *reinterpret_cast<const float2*>(b2 + e * 256 + d0 + col);
                #pragma unroll
                for (int p = 0; p < 2; p++) {
                    int r = wm * 32 + mt * 16 + gid + p * 8;
                    float v0 = fmaxf(t[mt][nt][p * 2 + 0] + bv.x, 0.f);
                    float v1 = fmaxf(t[mt][nt][p * 2 + 1] + bv.y, 0.f);
                    if (g == 0) {
                        float ga = sg[(0 * 64 + r) * 12 + e], gs = sg[(1 * 64 + r) * 12 + e];
                        oA[mt][nt][p * 2 + 0] += ga * v0; oA[mt][nt][p * 2 + 1] += ga * v1;
                        oS[mt][nt][p * 2 + 0] += gs * v0; oS[mt][nt][p * 2 + 1] += gs * v1;
                    } else if (g == 1) {
                        float ga = sg[(0 * 64 + r) * 12 + 4 + e];
                        float gs = sg[(1 * 64 + r) * 12 + 4 + e];
                        float gb = sg[(2 * 64 + r) * 12 + 4 + e];
                        oA[mt][nt][p * 2 + 0] += ga * v0; oA[mt][nt][p * 2 + 1] += ga * v1;
                        oS[mt][nt][p * 2 + 0] += gs * v0; oS[mt][nt][p * 2 + 1] += gs * v1;
                        oB[mt][nt][p * 2 + 0] += gb * v0; oB[mt][nt][p * 2 + 1] += gb * v1;
                    } else {
                        float gs = sg[(1 * 64 + r) * 12 + 8 + e];
                        float gb = sg[(2 * 64 + r) * 12 + e];
                        oS[mt][nt][p * 2 + 0] += gs * v0; oS[mt][nt][p * 2 + 1] += gs * v1;
                        oB[mt][nt][p * 2 + 0] += gb * v0; oB[mt][nt][p * 2 + 1] += gb * v1;
                    }
                }
            }
        }
        __syncthreads();
    }

    #pragma unroll
    for (int mt = 0; mt < 2; mt++) {
        #pragma unroll
        for (int nt = 0; nt < 2; nt++) {
            int col = d0 + wn * 16 + nt * 8 + quad * 2;
            #pragma unroll
            for (int p = 0; p < 2; p++) {
                int row = row0 + wm * 32 + mt * 16 + gid + p * 8;
                size_t base = (size_t)row * 256 + col;
                float2 vA; vA.x = oA[mt][nt][p * 2]; vA.y = oA[mt][nt][p * 2 + 1];
                float2 vS; vS.x = oS[mt][nt][p * 2]; vS.y = oS[mt][nt][p * 2 + 1];
                float2 vB; vB.x = oB[mt][nt][p * 2]; vB.y = oB[mt][nt][p * 2 + 1];
                *reinterpret_cast<float2*>(out + base) = vA;
                *reinterpret_cast<float2*>(out + (size_t)NB * 256 + base) = vS;
                *reinterpret_cast<float2*>(out + 2ull * NB * 256 + base) = vB;
            }
        }
    }
}

extern "C" void kernel_launch(void* const* d_in, const int* in_sizes, int n_in,
                              void* d_out, int out_size)
{
    const float* xA  = (const float*)d_in[0];
    const float* xS  = (const float*)d_in[1];
    const float* xB  = (const float*)d_in[2];
    const float* W1A = (const float*)d_in[3];
    const float* b1A = (const float*)d_in[4];
    const float* W2A = (const float*)d_in[5];
    const float* b2A = (const float*)d_in[6];
    const float* W1S = (const float*)d_in[7];
    const float* b1S = (const float*)d_in[8];
    const float* W2S = (const float*)d_in[9];
    const float* b2S = (const float*)d_in[10];
    const float* W1B = (const float*)d_in[11];
    const float* b1B = (const float*)d_in[12];
    const float* W2B = (const float*)d_in[13];
    const float* b2B = (const float*)d_in[14];
    const float* WgA = (const float*)d_in[15];
    const float* bgA = (const float*)d_in[16];
    const float* WgB = (const float*)d_in[17];
    const float* bgB = (const float*)d_in[18];
    const float* WgS = (const float*)d_in[19];
    const float* bgS = (const float*)d_in[20];
    float* out = (float*)d_out;

    pack_w1_kernel<<<(3 * 288 * 1024 + 255) / 256, 256>>>(W1A, W1S, W1B, WgA, WgS, WgB);
    pack_w2_kernel<<<(3 * 4 * 256 * 64 + 255) / 256, 256>>>(W2A, W2S, W2B);

    cudaFuncSetAttribute(layer1_kernel, cudaFuncAttributeMaxDynamicSharedMemorySize, L1_SM);
    layer1_kernel<<<dim3(NB / 128, 1, 3), 256, L1_SM>>>(xA, xS, xB, b1A, b1S, b1B, bgA, bgS, bgB);

    cudaFuncSetAttribute(layer2_kernel, cudaFuncAttributeMaxDynamicSharedMemorySize, L2_SM);
    layer2_kernel<<<dim3(256 / 64, NB / 64), 256, L2_SM>>>(b2A, b2S, b2B, out);
}